// round 6
// baseline (speedup 1.0000x reference)
#include <cuda_runtime.h>
#include <cuda_fp16.h>

namespace {

constexpr int NS      = 512;     // matrix dim (S = K = O = 512)
constexpr int TM      = 64;      // block tile rows
constexpr int TN      = 64;      // block tile cols
constexpr int TK      = 64;      // k chunk (floats); 32 half2 pairs
constexpr int NCHUNK  = NS / TK; // 8
constexpr int THREADS = 256;
constexpr int KP      = TK / 2;  // 32 k-pairs per chunk
constexpr int ASTR    = KP + 2;  // As2 row stride (half2): 34 -> even (STS.64 align), odd/2 bank spread

__global__ __launch_bounds__(THREADS, 1)
void fuzzy_compose_h2_db_kernel(const float* __restrict__ t, float* __restrict__ out)
{
    // Double-buffered tiles.
    // A tile: [buf][m][kpair] half2 = (A[m,2kp], A[m,2kp+1]), row stride 34 half2
    __shared__ __half2 As2[2][TM][ASTR];   // 17.4 KB
    // B tile: [buf][kpair][n] half2 = (B[2kp,n], B[2kp+1,n])
    __shared__ __half2 Bs2[2][KP][TN];     // 16.4 KB

    const int comp = blockIdx.z;             // 0: t0∘t0, 1: t0∘t1
    const int bm   = blockIdx.y * TM;
    const int bn   = blockIdx.x * TN;

    const float* __restrict__ A = t;                     // t0 (left operand of both rules)
    const float* __restrict__ B = t + comp * (NS * NS);  // t[comp] (right operand)

    const int tid = threadIdx.x;
    const int tx  = tid & 15;       // n direction (16)
    const int ty  = tid >> 4;       // m direction (16)
    const int m0  = ty * 4;
    const int n0  = tx * 4;         // half2 columns == float columns

    // ---- loader indices ----
    const int lr = tid >> 4;        // 0..15 (A row base / B k-pair base)
    const int lc = (tid & 15) * 4;  // float column 0..60

    __half2 acc[4][4];
    const __half2 h2zero = __float2half2_rn(0.0f);  // inputs in [0,1): 0 is max-identity
#pragma unroll
    for (int i = 0; i < 4; ++i)
#pragma unroll
        for (int j = 0; j < 4; ++j) acc[i][j] = h2zero;

    float4 ra[4];   // A rows lr, lr+16, lr+32, lr+48 at cols [k0+lc, +4)
    float4 rb[4];   // B rows k0+2lr, +1, k0+32+2lr, +1 at cols [bn+lc, +4)

    auto ldg_chunk = [&](int c) {
        const int k0 = c * TK;
#pragma unroll
        for (int i = 0; i < 4; ++i)
            ra[i] = *reinterpret_cast<const float4*>(&A[(bm + lr + 16 * i) * NS + k0 + lc]);
        rb[0] = *reinterpret_cast<const float4*>(&B[(k0 + 2 * lr    ) * NS + bn + lc]);
        rb[1] = *reinterpret_cast<const float4*>(&B[(k0 + 2 * lr + 1) * NS + bn + lc]);
        rb[2] = *reinterpret_cast<const float4*>(&B[(k0 + 32 + 2 * lr    ) * NS + bn + lc]);
        rb[3] = *reinterpret_cast<const float4*>(&B[(k0 + 32 + 2 * lr + 1) * NS + bn + lc]);
    };

    auto sts_chunk = [&](int buf) {
        // A: each float4 covers k..k+3 -> two k-adjacent half2; one STS.64 per row
#pragma unroll
        for (int i = 0; i < 4; ++i) {
            __half2 h0 = __floats2half2_rn(ra[i].x, ra[i].y);
            __half2 h1 = __floats2half2_rn(ra[i].z, ra[i].w);
            uint2 pk;
            pk.x = *reinterpret_cast<unsigned int*>(&h0);
            pk.y = *reinterpret_cast<unsigned int*>(&h1);
            *reinterpret_cast<uint2*>(&As2[buf][lr + 16 * i][lc / 2]) = pk;
        }
        // B: interleave even/odd k rows into (k,k+1) half2 per n col; STS.128
#pragma unroll
        for (int j = 0; j < 2; ++j) {
            const float4 e = rb[2 * j];
            const float4 o = rb[2 * j + 1];
            __half2 b0 = __floats2half2_rn(e.x, o.x);
            __half2 b1 = __floats2half2_rn(e.y, o.y);
            __half2 b2 = __floats2half2_rn(e.z, o.z);
            __half2 b3 = __floats2half2_rn(e.w, o.w);
            uint4 pk;
            pk.x = *reinterpret_cast<unsigned int*>(&b0);
            pk.y = *reinterpret_cast<unsigned int*>(&b1);
            pk.z = *reinterpret_cast<unsigned int*>(&b2);
            pk.w = *reinterpret_cast<unsigned int*>(&b3);
            *reinterpret_cast<uint4*>(&Bs2[buf][lr + 16 * j][lc]) = pk;
        }
    };

    // ---- prologue: fill buffer 0, prefetch chunk 1 into registers ----
    ldg_chunk(0);
    sts_chunk(0);
    if (NCHUNK > 1) ldg_chunk(1);
    __syncthreads();

    for (int c = 0; c < NCHUNK; ++c) {
        const int buf = c & 1;

        // Stage chunk c+1 into the other buffer (its last readers synced at end of c-1),
        // then refill registers with chunk c+2. Both overlap the compute below.
        if (c + 1 < NCHUNK) {
            sts_chunk(buf ^ 1);
            if (c + 2 < NCHUNK) ldg_chunk(c + 2);
        }

#pragma unroll
        for (int kp = 0; kp < KP; ++kp) {
            const __half2 a0 = As2[buf][m0 + 0][kp];
            const __half2 a1 = As2[buf][m0 + 1][kp];
            const __half2 a2 = As2[buf][m0 + 2][kp];
            const __half2 a3 = As2[buf][m0 + 3][kp];

            const uint4 bv = *reinterpret_cast<const uint4*>(&Bs2[buf][kp][n0]);
            const __half2 b0 = *reinterpret_cast<const __half2*>(&bv.x);
            const __half2 b1 = *reinterpret_cast<const __half2*>(&bv.y);
            const __half2 b2 = *reinterpret_cast<const __half2*>(&bv.z);
            const __half2 b3 = *reinterpret_cast<const __half2*>(&bv.w);

            acc[0][0] = __hmax2(acc[0][0], __hmin2(a0, b0));
            acc[0][1] = __hmax2(acc[0][1], __hmin2(a0, b1));
            acc[0][2] = __hmax2(acc[0][2], __hmin2(a0, b2));
            acc[0][3] = __hmax2(acc[0][3], __hmin2(a0, b3));

            acc[1][0] = __hmax2(acc[1][0], __hmin2(a1, b0));
            acc[1][1] = __hmax2(acc[1][1], __hmin2(a1, b1));
            acc[1][2] = __hmax2(acc[1][2], __hmin2(a1, b2));
            acc[1][3] = __hmax2(acc[1][3], __hmin2(a1, b3));

            acc[2][0] = __hmax2(acc[2][0], __hmin2(a2, b0));
            acc[2][1] = __hmax2(acc[2][1], __hmin2(a2, b1));
            acc[2][2] = __hmax2(acc[2][2], __hmin2(a2, b2));
            acc[2][3] = __hmax2(acc[2][3], __hmin2(a2, b3));

            acc[3][0] = __hmax2(acc[3][0], __hmin2(a3, b0));
            acc[3][1] = __hmax2(acc[3][1], __hmin2(a3, b1));
            acc[3][2] = __hmax2(acc[3][2], __hmin2(a3, b2));
            acc[3][3] = __hmax2(acc[3][3], __hmin2(a3, b3));
        }

        if (c + 1 < NCHUNK) __syncthreads();   // buf^1 visible; buf free for next STS
    }

    // ---- epilogue: fold k-pair lanes, then out = t + num*(1 - t), t = t[comp] ----
    float* __restrict__ O = out + comp * (NS * NS);
#pragma unroll
    for (int i = 0; i < 4; ++i) {
        const int row = bm + m0 + i;
        const float4 tv = *reinterpret_cast<const float4*>(&B[row * NS + bn + n0]);
        float4 r;
        const float n00 = fmaxf(__low2float(acc[i][0]), __high2float(acc[i][0]));
        const float n01 = fmaxf(__low2float(acc[i][1]), __high2float(acc[i][1]));
        const float n02 = fmaxf(__low2float(acc[i][2]), __high2float(acc[i][2]));
        const float n03 = fmaxf(__low2float(acc[i][3]), __high2float(acc[i][3]));
        r.x = tv.x + n00 * (1.0f - tv.x);
        r.y = tv.y + n01 * (1.0f - tv.y);
        r.z = tv.z + n02 * (1.0f - tv.z);
        r.w = tv.w + n03 * (1.0f - tv.w);
        *reinterpret_cast<float4*>(&O[row * NS + bn + n0]) = r;
    }
}

} // namespace

extern "C" void kernel_launch(void* const* d_in, const int* in_sizes, int n_in,
                              void* d_out, int out_size)
{
    (void)in_sizes; (void)n_in; (void)out_size;
    const float* t = reinterpret_cast<const float*>(d_in[0]);
    float* out     = reinterpret_cast<float*>(d_out);

    dim3 grid(NS / TN, NS / TM, 2);   // 8 x 8 x 2 = 128 blocks
    fuzzy_compose_h2_db_kernel<<<grid, THREADS>>>(t, out);
}

// round 9
// speedup vs baseline: 1.6055x; 1.6055x over previous
#include <cuda_runtime.h>
#include <cuda_fp16.h>

namespace {

constexpr int NS      = 512;     // matrix dim (S = K = O = 512)
constexpr int TM      = 64;      // block tile rows
constexpr int TN      = 64;      // block tile cols
constexpr int TK      = 64;      // k chunk (floats); 32 half2 pairs
constexpr int NCHUNK  = NS / TK; // 8
constexpr int THREADS = 256;
constexpr int KP      = TK / 2;  // 32 k-pairs per chunk
constexpr int ASTR    = KP + 2;  // As2 row stride (half2) = 34: EVEN (STS.64 8B-aligned),
                                 // rows differ by 2 banks -> conflict-free broadcast reads

__global__ __launch_bounds__(THREADS, 1)
void fuzzy_compose_h2_kernel(const float* __restrict__ t, float* __restrict__ out)
{
    // A tile: [m][kpair] half2 = (A[m,2kp], A[m,2kp+1]), row stride 34 half2
    __shared__ __half2 As2[TM][ASTR];   // 8.7 KB
    // B tile: [kpair][n] half2 = (B[2kp,n], B[2kp+1,n])
    __shared__ __half2 Bs2[KP][TN];     // 8.2 KB

    const int comp = blockIdx.z;             // 0: t0∘t0, 1: t0∘t1
    const int bm   = blockIdx.y * TM;
    const int bn   = blockIdx.x * TN;

    const float* __restrict__ A = t;                     // t0 (left operand of both rules)
    const float* __restrict__ B = t + comp * (NS * NS);  // t[comp] (right operand)

    const int tid = threadIdx.x;
    const int tx  = tid & 15;       // n direction (16)
    const int ty  = tid >> 4;       // m direction (16)
    const int m0  = ty * 4;
    const int n0  = tx * 4;         // half2 columns == float columns

    // ---- loader indices ----
    const int lr = tid >> 4;        // 0..15 (A row base / B k-pair base)
    const int lc = (tid & 15) * 4;  // float column 0..60 (lc/2 even -> STS.64 aligned)

    __half2 acc[4][4];
    const __half2 h2zero = __float2half2_rn(0.0f);  // inputs in [0,1): 0 is max-identity
#pragma unroll
    for (int i = 0; i < 4; ++i)
#pragma unroll
        for (int j = 0; j < 4; ++j) acc[i][j] = h2zero;

    // ---- register prefetch of chunk 0 ----
    float4 ra0 = *reinterpret_cast<const float4*>(&A[(bm + lr     ) * NS + lc]);
    float4 ra1 = *reinterpret_cast<const float4*>(&A[(bm + lr + 16) * NS + lc]);
    float4 ra2 = *reinterpret_cast<const float4*>(&A[(bm + lr + 32) * NS + lc]);
    float4 ra3 = *reinterpret_cast<const float4*>(&A[(bm + lr + 48) * NS + lc]);
    float4 rb0 = *reinterpret_cast<const float4*>(&B[(2 * lr         ) * NS + bn + lc]);
    float4 rb1 = *reinterpret_cast<const float4*>(&B[(2 * lr + 1     ) * NS + bn + lc]);
    float4 rb2 = *reinterpret_cast<const float4*>(&B[(32 + 2 * lr    ) * NS + bn + lc]);
    float4 rb3 = *reinterpret_cast<const float4*>(&B[(32 + 2 * lr + 1) * NS + bn + lc]);

    for (int c = 0; c < NCHUNK; ++c) {
        __syncthreads();   // previous chunk's compute done (no-op first iter)

        // A: float4 covers k..k+3 -> two k-adjacent half2; STS.64 per row
        {
            __half2 h0 = __floats2half2_rn(ra0.x, ra0.y);
            __half2 h1 = __floats2half2_rn(ra0.z, ra0.w);
            uint2 p0; p0.x = *reinterpret_cast<unsigned int*>(&h0);
                      p0.y = *reinterpret_cast<unsigned int*>(&h1);
            *reinterpret_cast<uint2*>(&As2[lr][lc / 2]) = p0;

            h0 = __floats2half2_rn(ra1.x, ra1.y);
            h1 = __floats2half2_rn(ra1.z, ra1.w);
            uint2 p1; p1.x = *reinterpret_cast<unsigned int*>(&h0);
                      p1.y = *reinterpret_cast<unsigned int*>(&h1);
            *reinterpret_cast<uint2*>(&As2[lr + 16][lc / 2]) = p1;

            h0 = __floats2half2_rn(ra2.x, ra2.y);
            h1 = __floats2half2_rn(ra2.z, ra2.w);
            uint2 p2; p2.x = *reinterpret_cast<unsigned int*>(&h0);
                      p2.y = *reinterpret_cast<unsigned int*>(&h1);
            *reinterpret_cast<uint2*>(&As2[lr + 32][lc / 2]) = p2;

            h0 = __floats2half2_rn(ra3.x, ra3.y);
            h1 = __floats2half2_rn(ra3.z, ra3.w);
            uint2 p3; p3.x = *reinterpret_cast<unsigned int*>(&h0);
                      p3.y = *reinterpret_cast<unsigned int*>(&h1);
            *reinterpret_cast<uint2*>(&As2[lr + 48][lc / 2]) = p3;
        }
        // B: interleave even/odd k rows into (k,k+1) half2 per n col; STS.128
        {
            __half2 b0 = __floats2half2_rn(rb0.x, rb1.x);
            __half2 b1 = __floats2half2_rn(rb0.y, rb1.y);
            __half2 b2 = __floats2half2_rn(rb0.z, rb1.z);
            __half2 b3 = __floats2half2_rn(rb0.w, rb1.w);
            uint4 pk;
            pk.x = *reinterpret_cast<unsigned int*>(&b0);
            pk.y = *reinterpret_cast<unsigned int*>(&b1);
            pk.z = *reinterpret_cast<unsigned int*>(&b2);
            pk.w = *reinterpret_cast<unsigned int*>(&b3);
            *reinterpret_cast<uint4*>(&Bs2[lr][lc]) = pk;

            b0 = __floats2half2_rn(rb2.x, rb3.x);
            b1 = __floats2half2_rn(rb2.y, rb3.y);
            b2 = __floats2half2_rn(rb2.z, rb3.z);
            b3 = __floats2half2_rn(rb2.w, rb3.w);
            pk.x = *reinterpret_cast<unsigned int*>(&b0);
            pk.y = *reinterpret_cast<unsigned int*>(&b1);
            pk.z = *reinterpret_cast<unsigned int*>(&b2);
            pk.w = *reinterpret_cast<unsigned int*>(&b3);
            *reinterpret_cast<uint4*>(&Bs2[lr + 16][lc]) = pk;
        }
        __syncthreads();   // tiles visible

        if (c + 1 < NCHUNK) {
            const int kn = (c + 1) * TK;
            ra0 = *reinterpret_cast<const float4*>(&A[(bm + lr     ) * NS + kn + lc]);
            ra1 = *reinterpret_cast<const float4*>(&A[(bm + lr + 16) * NS + kn + lc]);
            ra2 = *reinterpret_cast<const float4*>(&A[(bm + lr + 32) * NS + kn + lc]);
            ra3 = *reinterpret_cast<const float4*>(&A[(bm + lr + 48) * NS + kn + lc]);
            rb0 = *reinterpret_cast<const float4*>(&B[(kn + 2 * lr         ) * NS + bn + lc]);
            rb1 = *reinterpret_cast<const float4*>(&B[(kn + 2 * lr + 1     ) * NS + bn + lc]);
            rb2 = *reinterpret_cast<const float4*>(&B[(kn + 32 + 2 * lr    ) * NS + bn + lc]);
            rb3 = *reinterpret_cast<const float4*>(&B[(kn + 32 + 2 * lr + 1) * NS + bn + lc]);
        }

#pragma unroll
        for (int kp = 0; kp < KP; ++kp) {
            const __half2 a0 = As2[m0 + 0][kp];
            const __half2 a1 = As2[m0 + 1][kp];
            const __half2 a2 = As2[m0 + 2][kp];
            const __half2 a3 = As2[m0 + 3][kp];

            const uint4 bv = *reinterpret_cast<const uint4*>(&Bs2[kp][n0]);
            const __half2 b0 = *reinterpret_cast<const __half2*>(&bv.x);
            const __half2 b1 = *reinterpret_cast<const __half2*>(&bv.y);
            const __half2 b2 = *reinterpret_cast<const __half2*>(&bv.z);
            const __half2 b3 = *reinterpret_cast<const __half2*>(&bv.w);

            acc[0][0] = __hmax2(acc[0][0], __hmin2(a0, b0));
            acc[0][1] = __hmax2(acc[0][1], __hmin2(a0, b1));
            acc[0][2] = __hmax2(acc[0][2], __hmin2(a0, b2));
            acc[0][3] = __hmax2(acc[0][3], __hmin2(a0, b3));

            acc[1][0] = __hmax2(acc[1][0], __hmin2(a1, b0));
            acc[1][1] = __hmax2(acc[1][1], __hmin2(a1, b1));
            acc[1][2] = __hmax2(acc[1][2], __hmin2(a1, b2));
            acc[1][3] = __hmax2(acc[1][3], __hmin2(a1, b3));

            acc[2][0] = __hmax2(acc[2][0], __hmin2(a2, b0));
            acc[2][1] = __hmax2(acc[2][1], __hmin2(a2, b1));
            acc[2][2] = __hmax2(acc[2][2], __hmin2(a2, b2));
            acc[2][3] = __hmax2(acc[2][3], __hmin2(a2, b3));

            acc[3][0] = __hmax2(acc[3][0], __hmin2(a3, b0));
            acc[3][1] = __hmax2(acc[3][1], __hmin2(a3, b1));
            acc[3][2] = __hmax2(acc[3][2], __hmin2(a3, b2));
            acc[3][3] = __hmax2(acc[3][3], __hmin2(a3, b3));
        }
    }

    // ---- epilogue: fold k-pair lanes, then out = t + num*(1 - t), t = t[comp] ----
    float* __restrict__ O = out + comp * (NS * NS);
#pragma unroll
    for (int i = 0; i < 4; ++i) {
        const int row = bm + m0 + i;
        const float4 tv = *reinterpret_cast<const float4*>(&B[row * NS + bn + n0]);
        float4 r;
        const float n00 = fmaxf(__low2float(acc[i][0]), __high2float(acc[i][0]));
        const float n01 = fmaxf(__low2float(acc[i][1]), __high2float(acc[i][1]));
        const float n02 = fmaxf(__low2float(acc[i][2]), __high2float(acc[i][2]));
        const float n03 = fmaxf(__low2float(acc[i][3]), __high2float(acc[i][3]));
        r.x = tv.x + n00 * (1.0f - tv.x);
        r.y = tv.y + n01 * (1.0f - tv.y);
        r.z = tv.z + n02 * (1.0f - tv.z);
        r.w = tv.w + n03 * (1.0f - tv.w);
        *reinterpret_cast<float4*>(&O[row * NS + bn + n0]) = r;
    }
}

} // namespace

extern "C" void kernel_launch(void* const* d_in, const int* in_sizes, int n_in,
                              void* d_out, int out_size)
{
    (void)in_sizes; (void)n_in; (void)out_size;
    const float* t = reinterpret_cast<const float*>(d_in[0]);
    float* out     = reinterpret_cast<float*>(d_out);

    dim3 grid(NS / TN, NS / TM, 2);   // 8 x 8 x 2 = 128 blocks
    fuzzy_compose_h2_kernel<<<grid, THREADS>>>(t, out);
}

// round 11
// speedup vs baseline: 1.6278x; 1.0139x over previous
#include <cuda_runtime.h>
#include <cuda_fp16.h>

namespace {

constexpr int NS      = 512;     // matrix dim (S = K = O = 512)
constexpr int TM      = 32;      // block tile rows
constexpr int TN      = 64;      // block tile cols
constexpr int TK      = 64;      // k chunk (floats); 32 half2 pairs
constexpr int NCHUNK  = NS / TK; // 8
constexpr int THREADS = 128;     // 2 CTAs/SM -> two independent barrier domains
constexpr int KP      = TK / 2;  // 32 k-pairs per chunk
constexpr int ASTR    = KP + 2;  // As2 row stride (half2) = 34: EVEN (STS.64 8B-aligned),
                                 // adjacent rows 2 banks apart -> conflict-free broadcast reads

__global__ __launch_bounds__(THREADS, 2)
void fuzzy_compose_h2_kernel(const float* __restrict__ t, float* __restrict__ out)
{
    // A tile: [m][kpair] half2 = (A[m,2kp], A[m,2kp+1]), row stride 34 half2
    __shared__ __half2 As2[TM][ASTR];   // 4.4 KB
    // B tile: [kpair][n] half2 = (B[2kp,n], B[2kp+1,n])
    __shared__ __half2 Bs2[KP][TN];     // 8.2 KB

    const int comp = blockIdx.z;             // 0: t0∘t0, 1: t0∘t1
    const int bm   = blockIdx.y * TM;
    const int bn   = blockIdx.x * TN;

    const float* __restrict__ A = t;                     // t0 (left operand of both rules)
    const float* __restrict__ B = t + comp * (NS * NS);  // t[comp] (right operand)

    const int tid = threadIdx.x;
    const int tx  = tid & 15;       // n direction (16)
    const int ty  = tid >> 4;       // m direction (8)
    const int m0  = ty * 4;
    const int n0  = tx * 4;         // half2 columns == float columns

    // ---- loader indices ----
    const int lr = tid >> 4;        // 0..7 (A row base / B k-pair base)
    const int lc = (tid & 15) * 4;  // float column 0..60 (lc/2 even -> STS.64 aligned)

    __half2 acc[4][4];
    const __half2 h2zero = __float2half2_rn(0.0f);  // inputs in [0,1): 0 is max-identity
#pragma unroll
    for (int i = 0; i < 4; ++i)
#pragma unroll
        for (int j = 0; j < 4; ++j) acc[i][j] = h2zero;

    // ---- register prefetch of chunk 0 ----
    // A tile 32 rows x 64 cols: rows lr, lr+8, lr+16, lr+24
    float4 ra0 = *reinterpret_cast<const float4*>(&A[(bm + lr     ) * NS + lc]);
    float4 ra1 = *reinterpret_cast<const float4*>(&A[(bm + lr +  8) * NS + lc]);
    float4 ra2 = *reinterpret_cast<const float4*>(&A[(bm + lr + 16) * NS + lc]);
    float4 ra3 = *reinterpret_cast<const float4*>(&A[(bm + lr + 24) * NS + lc]);
    // B tile 64 k-rows x 64 cols: k-pairs lr, lr+8, lr+16, lr+24 (even/odd row each)
    float4 rb0e = *reinterpret_cast<const float4*>(&B[(2 * (lr     )    ) * NS + bn + lc]);
    float4 rb0o = *reinterpret_cast<const float4*>(&B[(2 * (lr     ) + 1) * NS + bn + lc]);
    float4 rb1e = *reinterpret_cast<const float4*>(&B[(2 * (lr +  8)    ) * NS + bn + lc]);
    float4 rb1o = *reinterpret_cast<const float4*>(&B[(2 * (lr +  8) + 1) * NS + bn + lc]);
    float4 rb2e = *reinterpret_cast<const float4*>(&B[(2 * (lr + 16)    ) * NS + bn + lc]);
    float4 rb2o = *reinterpret_cast<const float4*>(&B[(2 * (lr + 16) + 1) * NS + bn + lc]);
    float4 rb3e = *reinterpret_cast<const float4*>(&B[(2 * (lr + 24)    ) * NS + bn + lc]);
    float4 rb3o = *reinterpret_cast<const float4*>(&B[(2 * (lr + 24) + 1) * NS + bn + lc]);

    for (int c = 0; c < NCHUNK; ++c) {
        __syncthreads();   // previous chunk's compute done (no-op first iter)

        // A: float4 covers k..k+3 -> two k-adjacent half2; STS.64 per row
        {
            __half2 h0 = __floats2half2_rn(ra0.x, ra0.y);
            __half2 h1 = __floats2half2_rn(ra0.z, ra0.w);
            uint2 p; p.x = *reinterpret_cast<unsigned int*>(&h0);
                     p.y = *reinterpret_cast<unsigned int*>(&h1);
            *reinterpret_cast<uint2*>(&As2[lr][lc / 2]) = p;

            h0 = __floats2half2_rn(ra1.x, ra1.y);
            h1 = __floats2half2_rn(ra1.z, ra1.w);
            p.x = *reinterpret_cast<unsigned int*>(&h0);
            p.y = *reinterpret_cast<unsigned int*>(&h1);
            *reinterpret_cast<uint2*>(&As2[lr + 8][lc / 2]) = p;

            h0 = __floats2half2_rn(ra2.x, ra2.y);
            h1 = __floats2half2_rn(ra2.z, ra2.w);
            p.x = *reinterpret_cast<unsigned int*>(&h0);
            p.y = *reinterpret_cast<unsigned int*>(&h1);
            *reinterpret_cast<uint2*>(&As2[lr + 16][lc / 2]) = p;

            h0 = __floats2half2_rn(ra3.x, ra3.y);
            h1 = __floats2half2_rn(ra3.z, ra3.w);
            p.x = *reinterpret_cast<unsigned int*>(&h0);
            p.y = *reinterpret_cast<unsigned int*>(&h1);
            *reinterpret_cast<uint2*>(&As2[lr + 24][lc / 2]) = p;
        }
        // B: interleave even/odd k rows into (k,k+1) half2 per n col; STS.128
        {
            uint4 pk;
            __half2 b0 = __floats2half2_rn(rb0e.x, rb0o.x);
            __half2 b1 = __floats2half2_rn(rb0e.y, rb0o.y);
            __half2 b2 = __floats2half2_rn(rb0e.z, rb0o.z);
            __half2 b3 = __floats2half2_rn(rb0e.w, rb0o.w);
            pk.x = *reinterpret_cast<unsigned int*>(&b0);
            pk.y = *reinterpret_cast<unsigned int*>(&b1);
            pk.z = *reinterpret_cast<unsigned int*>(&b2);
            pk.w = *reinterpret_cast<unsigned int*>(&b3);
            *reinterpret_cast<uint4*>(&Bs2[lr][lc]) = pk;

            b0 = __floats2half2_rn(rb1e.x, rb1o.x);
            b1 = __floats2half2_rn(rb1e.y, rb1o.y);
            b2 = __floats2half2_rn(rb1e.z, rb1o.z);
            b3 = __floats2half2_rn(rb1e.w, rb1o.w);
            pk.x = *reinterpret_cast<unsigned int*>(&b0);
            pk.y = *reinterpret_cast<unsigned int*>(&b1);
            pk.z = *reinterpret_cast<unsigned int*>(&b2);
            pk.w = *reinterpret_cast<unsigned int*>(&b3);
            *reinterpret_cast<uint4*>(&Bs2[lr + 8][lc]) = pk;

            b0 = __floats2half2_rn(rb2e.x, rb2o.x);
            b1 = __floats2half2_rn(rb2e.y, rb2o.y);
            b2 = __floats2half2_rn(rb2e.z, rb2o.z);
            b3 = __floats2half2_rn(rb2e.w, rb2o.w);
            pk.x = *reinterpret_cast<unsigned int*>(&b0);
            pk.y = *reinterpret_cast<unsigned int*>(&b1);
            pk.z = *reinterpret_cast<unsigned int*>(&b2);
            pk.w = *reinterpret_cast<unsigned int*>(&b3);
            *reinterpret_cast<uint4*>(&Bs2[lr + 16][lc]) = pk;

            b0 = __floats2half2_rn(rb3e.x, rb3o.x);
            b1 = __floats2half2_rn(rb3e.y, rb3o.y);
            b2 = __floats2half2_rn(rb3e.z, rb3o.z);
            b3 = __floats2half2_rn(rb3e.w, rb3o.w);
            pk.x = *reinterpret_cast<unsigned int*>(&b0);
            pk.y = *reinterpret_cast<unsigned int*>(&b1);
            pk.z = *reinterpret_cast<unsigned int*>(&b2);
            pk.w = *reinterpret_cast<unsigned int*>(&b3);
            *reinterpret_cast<uint4*>(&Bs2[lr + 24][lc]) = pk;
        }
        __syncthreads();   // tiles visible

        if (c + 1 < NCHUNK) {
            const int kn = (c + 1) * TK;
            ra0 = *reinterpret_cast<const float4*>(&A[(bm + lr     ) * NS + kn + lc]);
            ra1 = *reinterpret_cast<const float4*>(&A[(bm + lr +  8) * NS + kn + lc]);
            ra2 = *reinterpret_cast<const float4*>(&A[(bm + lr + 16) * NS + kn + lc]);
            ra3 = *reinterpret_cast<const float4*>(&A[(bm + lr + 24) * NS + kn + lc]);
            rb0e = *reinterpret_cast<const float4*>(&B[(kn + 2 * (lr     )    ) * NS + bn + lc]);
            rb0o = *reinterpret_cast<const float4*>(&B[(kn + 2 * (lr     ) + 1) * NS + bn + lc]);
            rb1e = *reinterpret_cast<const float4*>(&B[(kn + 2 * (lr +  8)    ) * NS + bn + lc]);
            rb1o = *reinterpret_cast<const float4*>(&B[(kn + 2 * (lr +  8) + 1) * NS + bn + lc]);
            rb2e = *reinterpret_cast<const float4*>(&B[(kn + 2 * (lr + 16)    ) * NS + bn + lc]);
            rb2o = *reinterpret_cast<const float4*>(&B[(kn + 2 * (lr + 16) + 1) * NS + bn + lc]);
            rb3e = *reinterpret_cast<const float4*>(&B[(kn + 2 * (lr + 24)    ) * NS + bn + lc]);
            rb3o = *reinterpret_cast<const float4*>(&B[(kn + 2 * (lr + 24) + 1) * NS + bn + lc]);
        }

#pragma unroll
        for (int kp = 0; kp < KP; ++kp) {
            const __half2 a0 = As2[m0 + 0][kp];
            const __half2 a1 = As2[m0 + 1][kp];
            const __half2 a2 = As2[m0 + 2][kp];
            const __half2 a3 = As2[m0 + 3][kp];

            const uint4 bv = *reinterpret_cast<const uint4*>(&Bs2[kp][n0]);
            const __half2 b0 = *reinterpret_cast<const __half2*>(&bv.x);
            const __half2 b1 = *reinterpret_cast<const __half2*>(&bv.y);
            const __half2 b2 = *reinterpret_cast<const __half2*>(&bv.z);
            const __half2 b3 = *reinterpret_cast<const __half2*>(&bv.w);

            acc[0][0] = __hmax2(acc[0][0], __hmin2(a0, b0));
            acc[0][1] = __hmax2(acc[0][1], __hmin2(a0, b1));
            acc[0][2] = __hmax2(acc[0][2], __hmin2(a0, b2));
            acc[0][3] = __hmax2(acc[0][3], __hmin2(a0, b3));

            acc[1][0] = __hmax2(acc[1][0], __hmin2(a1, b0));
            acc[1][1] = __hmax2(acc[1][1], __hmin2(a1, b1));
            acc[1][2] = __hmax2(acc[1][2], __hmin2(a1, b2));
            acc[1][3] = __hmax2(acc[1][3], __hmin2(a1, b3));

            acc[2][0] = __hmax2(acc[2][0], __hmin2(a2, b0));
            acc[2][1] = __hmax2(acc[2][1], __hmin2(a2, b1));
            acc[2][2] = __hmax2(acc[2][2], __hmin2(a2, b2));
            acc[2][3] = __hmax2(acc[2][3], __hmin2(a2, b3));

            acc[3][0] = __hmax2(acc[3][0], __hmin2(a3, b0));
            acc[3][1] = __hmax2(acc[3][1], __hmin2(a3, b1));
            acc[3][2] = __hmax2(acc[3][2], __hmin2(a3, b2));
            acc[3][3] = __hmax2(acc[3][3], __hmin2(a3, b3));
        }
    }

    // ---- epilogue: fold k-pair lanes, then out = t + num*(1 - t), t = t[comp] ----
    float* __restrict__ O = out + comp * (NS * NS);
#pragma unroll
    for (int i = 0; i < 4; ++i) {
        const int row = bm + m0 + i;
        const float4 tv = *reinterpret_cast<const float4*>(&B[row * NS + bn + n0]);
        float4 r;
        const float n00 = fmaxf(__low2float(acc[i][0]), __high2float(acc[i][0]));
        const float n01 = fmaxf(__low2float(acc[i][1]), __high2float(acc[i][1]));
        const float n02 = fmaxf(__low2float(acc[i][2]), __high2float(acc[i][2]));
        const float n03 = fmaxf(__low2float(acc[i][3]), __high2float(acc[i][3]));
        r.x = tv.x + n00 * (1.0f - tv.x);
        r.y = tv.y + n01 * (1.0f - tv.y);
        r.z = tv.z + n02 * (1.0f - tv.z);
        r.w = tv.w + n03 * (1.0f - tv.w);
        *reinterpret_cast<float4*>(&O[row * NS + bn + n0]) = r;
    }
}

} // namespace

extern "C" void kernel_launch(void* const* d_in, const int* in_sizes, int n_in,
                              void* d_out, int out_size)
{
    (void)in_sizes; (void)n_in; (void)out_size;
    const float* t = reinterpret_cast<const float*>(d_in[0]);
    float* out     = reinterpret_cast<float*>(d_out);

    dim3 grid(NS / TN, NS / TM, 2);   // 8 x 16 x 2 = 256 blocks, 2 CTAs/SM
    fuzzy_compose_h2_kernel<<<grid, THREADS>>>(t, out);
}